// round 16
// baseline (speedup 1.0000x reference)
#include <cuda_runtime.h>
#include <cuda_bf16.h>

// CRF forward scan, probability domain, tensor-pipe matvec.
// R16 = R14 champion algorithm with M split across EIGHT warps (256 thr):
// warp w owns states [16w, 16w+16) -> 8 HMMA/warp/step (2 chains of 4),
// 2 warps per SMSP so HMMA chains + LDS latency interleave across warps.
// Total HMMA per SMSP unchanged (16) -> no throughput cost, pure latency hiding.
// Kept from champion: conflict-free permuted smem (4x LDS.128 B-frags),
// every-step REDUX power-of-two renorm (twice proven load-bearing),
// unroll x2 static buffers, 3-deep y prefetch, one __syncthreads per step.

#define KDIM 128

__device__ __forceinline__ unsigned bpack(float lo, float hi) {
    unsigned r;
    asm("cvt.rn.bf16x2.f32 %0, %1, %2;" : "=r"(r) : "f"(hi), "f"(lo));
    return r;
}

#define MMA(C, A, Bv)                                                        \
    asm volatile(                                                            \
        "mma.sync.aligned.m16n8k16.row.col.f32.bf16.bf16.f32 "               \
        "{%0,%1,%2,%3},{%4,%5,%6,%7},{%8,%9},{%0,%1,%2,%3};"                 \
        : "+f"(C[0]), "+f"(C[1]), "+f"(C[2]), "+f"(C[3])                     \
        : "r"(A[0]), "r"(A[1]), "r"(A[2]), "r"(A[3]),                        \
          "r"(Bv[0]), "r"(Bv[1]))

__device__ __forceinline__ int permw(int w) {   // u32-word permutation
    return ((w >> 4) << 4) + ((w & 3) << 2) + ((w >> 2) & 3);
}

__global__ __launch_bounds__(256, 1)
void crf_fwd_kernel(const float* __restrict__ y,
                    const float* __restrict__ mask,
                    const float* __restrict__ trans,
                    float* __restrict__ out,
                    int T) {
    const int b    = blockIdx.x;
    const int tid  = threadIdx.x;
    const int lane = tid & 31;
    const int warp = tid >> 5;          // 0..7 : states [16w, 16w+16)
    const int g4   = lane >> 2;         // 0..7
    const int tig  = lane & 3;          // 0..3

    __shared__ __align__(16) unsigned shp[2][64];   // permuted state (bf16x2)
    __shared__ __align__(16) unsigned wmax[2][8];
    __shared__ float redf[8];
    __shared__ int   len_sh;

    // ---- one-time: E-tile rows [16w,16w+16) as mma A-fragments, 32 regs ----
    unsigned EA[8][4];
    {
        const int r0 = 16 * warp + g4;
        const float* tr0 = trans + (size_t)r0 * KDIM;
        const float* tr1 = tr0 + 8 * KDIM;
        #pragma unroll
        for (int kt = 0; kt < 8; kt++) {
            const int c0 = 16 * kt + 2 * tig;
            EA[kt][0] = bpack(expf(tr0[c0]),   expf(tr0[c0+1]));
            EA[kt][1] = bpack(expf(tr1[c0]),   expf(tr1[c0+1]));
            EA[kt][2] = bpack(expf(tr0[c0+8]), expf(tr0[c0+9]));
            EA[kt][3] = bpack(expf(tr1[c0+8]), expf(tr1[c0+9]));
        }
    }

    // ---- init state (permuted), renorm buffers, length ----
    if (tid == 0) len_sh = 0;
    if (tid < KDIM) {
        int p = permw(tid >> 1);
        reinterpret_cast<__nv_bfloat16*>(shp[0])[2 * p + (tid & 1)] =
            __float2bfloat16_rn((tid == 2) ? 1.0f : 0.0f);   // SOS_IDX = 2
    }
    if (tid < 16) wmax[tid >> 3][tid & 7] = 0x3f800000u;     // both slots 1.0
    __syncthreads();
    {
        const float* mb = mask + (size_t)b * T;
        int cnt = 0;
        for (int t = tid; t < T; t += 256) cnt += (mb[t] != 0.0f);
        cnt = __reduce_add_sync(0xffffffffu, cnt);
        if (lane == 0) atomicAdd(&len_sh, cnt);
    }
    __syncthreads();
    const int len = len_sh;

    // ---- y prefetch (3 deep); thread owns states m0 and m0+8 ----
    const int m0 = 16 * warp + g4;
    const float* yb   = y + (size_t)b * T * KDIM + m0;
    const float* yp   = yb + 3 * KDIM;
    const float* yend = yb + (size_t)T * KDIM;
    float ey0 = (len > 0) ? __expf(yb[0]) : 1.0f;
    float ey1 = (len > 0) ? __expf(yb[8]) : 1.0f;
    float yA0 = (1 < T) ? yb[KDIM]     : 0.0f;
    float yA1 = (1 < T) ? yb[KDIM + 8] : 0.0f;
    float yB0 = (2 < T) ? yb[2*KDIM]     : 0.0f;
    float yB1 = (2 < T) ? yb[2*KDIM + 8] : 0.0f;

    // store-side permuted bf16 indices for states m0 (k=0) and m0+8 (k=1)
    const int pidx0 = 2 * permw(8 * warp +     (g4 >> 1)) + (g4 & 1);
    const int pidx1 = 2 * permw(8 * warp + 4 + (g4 >> 1)) + (g4 & 1);

    float s0 = (warp == 0 && g4 == 2) ? 1.0f : 0.0f;   // for final reduce
    float s1 = 0.0f;
    int eacc = 0;

#define STEP(SRC, DST)                                                       \
    {                                                                        \
        /* 4x LDS.128 first: latency overlaps the renorm math below */       \
        const uint4* sp4 = reinterpret_cast<const uint4*>(shp[SRC]);         \
        uint4 q0 = sp4[tig], q1 = sp4[4 + tig];                              \
        uint4 q2 = sp4[8 + tig], q3 = sp4[12 + tig];                         \
        uint4 wma = *reinterpret_cast<const uint4*>(&wmax[SRC][0]);          \
        uint4 wmb = *reinterpret_cast<const uint4*>(&wmax[SRC][4]);          \
        unsigned mbits = max(max(max(wma.x, wma.y), max(wma.z, wma.w)),      \
                             max(max(wmb.x, wmb.y), max(wmb.z, wmb.w)));     \
        int Ee   = (int)(mbits >> 23);                                       \
        float rz = __uint_as_float((unsigned)(254 - Ee) << 23);              \
        eacc    += Ee - 127;                                                 \
        float ez0 = ey0 * rz, ez1 = ey1 * rz;                                \
        unsigned rb[8][2] = {{q0.x,q0.y},{q0.z,q0.w},{q1.x,q1.y},{q1.z,q1.w},\
                             {q2.x,q2.y},{q2.z,q2.w},{q3.x,q3.y},{q3.z,q3.w}};\
        /* 2 accumulate chains of depth 4 */                                 \
        float cP[4] = {0,0,0,0}, cQ[4] = {0,0,0,0};                          \
        _Pragma("unroll")                                                    \
        for (int kp = 0; kp < 4; kp++) {                                     \
            MMA(cP, EA[2*kp],   rb[2*kp]);                                   \
            MMA(cQ, EA[2*kp+1], rb[2*kp+1]);                                 \
        }                                                                    \
        s0 = (cP[0] + cQ[0]) * ez0;   /* state m0     */                     \
        s1 = (cP[2] + cQ[2]) * ez1;   /* state m0 + 8 */                     \
        __nv_bfloat16* sd = reinterpret_cast<__nv_bfloat16*>(shp[DST]);      \
        sd[pidx0] = __float2bfloat16_rn(s0);                                 \
        sd[pidx1] = __float2bfloat16_rn(s1);                                 \
        unsigned mm = max(__float_as_uint(s0), __float_as_uint(s1));         \
        mm = __reduce_max_sync(0xffffffffu, mm);                             \
        if (lane == 0) wmax[DST][warp] = mm;                                 \
        ey0 = __expf(yA0);  ey1 = __expf(yA1);                               \
        yA0 = yB0;          yA1 = yB1;                                       \
        yB0 = (yp < yend) ? yp[0] : 0.0f;                                    \
        yB1 = (yp < yend) ? yp[8] : 0.0f;                                    \
        yp += KDIM;                                                          \
        __syncthreads();                                                     \
    }

    const int len2 = len & ~1;
    for (int t = 0; t < len2; t += 2) {
        STEP(0, 1)
        STEP(1, 0)
    }
    if (len & 1) {
        STEP(0, 1)
    }
#undef STEP

    // ---- final: out[b] = log(sum_i s_i) + eacc*ln2 ----
    // each state held by 4 tig-duplicate lanes -> warp sum = 4x partial
    float e = s0 + s1;
    e += __shfl_xor_sync(0xffffffffu, e, 16);
    e += __shfl_xor_sync(0xffffffffu, e, 8);
    e += __shfl_xor_sync(0xffffffffu, e, 4);
    e += __shfl_xor_sync(0xffffffffu, e, 2);
    e += __shfl_xor_sync(0xffffffffu, e, 1);
    if (lane == 0) redf[warp] = e;
    __syncthreads();
    if (tid == 0) {
        float tot = ((redf[0] + redf[1]) + (redf[2] + redf[3])) +
                    ((redf[4] + redf[5]) + (redf[6] + redf[7]));
        out[b] = logf(tot * 0.25f) +
                 (float)((double)eacc * 0.6931471805599453);
    }
}

extern "C" void kernel_launch(void* const* d_in, const int* in_sizes, int n_in,
                              void* d_out, int out_size) {
    const float* y     = (const float*)d_in[0];   // (B, T, K) f32
    const float* mask  = (const float*)d_in[1];   // (B, T)    f32
    const float* trans = (const float*)d_in[2];   // (K, K)    f32
    float* out = (float*)d_out;                   // (B,)      f32

    const int B = out_size;                       // 64
    const int T = in_sizes[1] / B;                // 256

    crf_fwd_kernel<<<B, 256>>>(y, mask, trans, out, T);
}

// round 17
// speedup vs baseline: 1.1782x; 1.1782x over previous
#include <cuda_runtime.h>
#include <cuda_bf16.h>

// CRF forward scan, probability domain, tensor-pipe matvec.  CHAMPION frame:
// 1 CTA/batch, 128 threads (4 warps), warp w owns states [32w, 32w+32);
// mma.sync.m16n8k16 bf16->f32 with all 8 B-columns carrying the same state
// vector (broadcast trick). Conflict-free permuted smem layout: u32 word w at
// p(w) = (w>>4)*16 + (w&3)*4 + ((w>>2)&3); lane tig loads its 16 B-frag words
// as 4x LDS.128. Every-step REDUX power-of-two renorm (proven load-bearing),
// depth-4 HMMA chains (proven), unroll x2 static buffers, 3-deep y prefetch.
// R17: off-spine micro-trims only — unpredicated y prefetch via pointer clamp
// (over-fetched rows are never consumed), hoisted DST store pointers.

#define KDIM 128

__device__ __forceinline__ unsigned bpack(float lo, float hi) {
    unsigned r;
    asm("cvt.rn.bf16x2.f32 %0, %1, %2;" : "=r"(r) : "f"(hi), "f"(lo));
    return r;
}

#define MMA(C, A, Bv)                                                        \
    asm volatile(                                                            \
        "mma.sync.aligned.m16n8k16.row.col.f32.bf16.bf16.f32 "               \
        "{%0,%1,%2,%3},{%4,%5,%6,%7},{%8,%9},{%0,%1,%2,%3};"                 \
        : "+f"(C[0]), "+f"(C[1]), "+f"(C[2]), "+f"(C[3])                     \
        : "r"(A[0]), "r"(A[1]), "r"(A[2]), "r"(A[3]),                        \
          "r"(Bv[0]), "r"(Bv[1]))

__global__ __launch_bounds__(128, 1)
void crf_fwd_kernel(const float* __restrict__ y,
                    const float* __restrict__ mask,
                    const float* __restrict__ trans,
                    float* __restrict__ out,
                    int T) {
    const int b    = blockIdx.x;
    const int tid  = threadIdx.x;
    const int lane = tid & 31;
    const int warp = tid >> 5;          // 0..3 : states [32w, 32w+32)
    const int g4   = lane >> 2;         // 0..7
    const int tig  = lane & 3;          // 0..3

    // permuted state buffers (64 u32 words = 128 bf16 each)
    __shared__ __align__(16) unsigned shp[2][64];
    __shared__ __align__(16) unsigned wmax[2][4];
    __shared__ float redf[4];
    __shared__ int   len_sh;

    // ---- one-time: E = exp(trans) as mma A-fragments (bf16), 64 regs ----
    unsigned EA[2][8][4];
    #pragma unroll
    for (int mt = 0; mt < 2; mt++) {
        const int r0 = 32 * warp + 16 * mt + g4;
        const float* tr0 = trans + (size_t)r0 * KDIM;
        const float* tr1 = tr0 + 8 * KDIM;
        #pragma unroll
        for (int kt = 0; kt < 8; kt++) {
            const int c0 = 16 * kt + 2 * tig;
            EA[mt][kt][0] = bpack(expf(tr0[c0]),   expf(tr0[c0+1]));
            EA[mt][kt][1] = bpack(expf(tr1[c0]),   expf(tr1[c0+1]));
            EA[mt][kt][2] = bpack(expf(tr0[c0+8]), expf(tr0[c0+9]));
            EA[mt][kt][3] = bpack(expf(tr1[c0+8]), expf(tr1[c0+9]));
        }
    }

    // ---- init state (permuted), renorm buffers, length ----
    if (tid == 0) len_sh = 0;
    if (tid < KDIM) {
        int w = tid >> 1;
        int p = ((w >> 4) << 4) + ((w & 3) << 2) + ((w >> 2) & 3);
        reinterpret_cast<__nv_bfloat16*>(shp[0])[2 * p + (tid & 1)] =
            __float2bfloat16_rn((tid == 2) ? 1.0f : 0.0f);   // SOS_IDX = 2
    }
    if (tid < 8) wmax[tid >> 2][tid & 3] = 0x3f800000u;      // both slots 1.0
    __syncthreads();
    {
        const float* mb = mask + (size_t)b * T;
        int cnt = 0;
        for (int t = tid; t < T; t += KDIM) cnt += (mb[t] != 0.0f);
        cnt = __reduce_add_sync(0xffffffffu, cnt);
        if (lane == 0) atomicAdd(&len_sh, cnt);
    }
    __syncthreads();
    const int len = len_sh;

    // ---- y prefetch pipeline (3 deep); thread owns states m0+{0,8,16,24} ----
    // Unpredicated loads: pointer clamped to the LAST VALID ROW. Over-fetched
    // rows belong to steps >= len and their ey values are never consumed.
    const int m0 = 32 * warp + g4;
    const float* yb    = y + (size_t)b * T * KDIM + m0;
    const float* ylast = yb + (size_t)(T - 1) * KDIM;
    const float* yp    = yb + 3 * KDIM;
    float ey[4], yA[4], yB[4];
    {
        const float* y1 = (T > 1) ? yb + KDIM : ylast;
        const float* y2 = (T > 2) ? yb + 2 * KDIM : ylast;
        #pragma unroll
        for (int k = 0; k < 4; k++) {
            ey[k] = __expf(yb[8 * k]);
            yA[k] = y1[8 * k];
            yB[k] = y2[8 * k];
        }
    }

    // store-side permuted base: state 32w+8k+g4 -> bf16 idx
    //   32*warp + 8*(g4>>1) + 2k + (g4&1)
    const int sbase = 32 * warp + ((g4 >> 1) << 3) + (g4 & 1);
    __nv_bfloat16* const sd0 = reinterpret_cast<__nv_bfloat16*>(shp[0]) + sbase;
    __nv_bfloat16* const sd1 = reinterpret_cast<__nv_bfloat16*>(shp[1]) + sbase;

    float s0 = (warp == 0 && g4 == 2) ? 1.0f : 0.0f;   // for final reduce
    float s1 = 0.0f, s2 = 0.0f, s3 = 0.0f;
    int eacc = 0;

#define STEP(SRC, DST, SD)                                                   \
    {                                                                        \
        /* 4x LDS.128 first: latency overlaps the renorm math below */       \
        const uint4* sp4 = reinterpret_cast<const uint4*>(shp[SRC]);         \
        uint4 q0 = sp4[tig], q1 = sp4[4 + tig];                              \
        uint4 q2 = sp4[8 + tig], q3 = sp4[12 + tig];                         \
        uint4 wm4 = *reinterpret_cast<const uint4*>(wmax[SRC]);              \
        unsigned mbits = max(max(wm4.x, wm4.y), max(wm4.z, wm4.w));          \
        int Ee   = (int)(mbits >> 23);                                       \
        float rz = __uint_as_float((unsigned)(254 - Ee) << 23);              \
        eacc    += Ee - 127;                                                 \
        float ez0 = ey[0]*rz, ez1 = ey[1]*rz, ez2 = ey[2]*rz, ez3 = ey[3]*rz;\
        unsigned rb[8][2] = {{q0.x,q0.y},{q0.z,q0.w},{q1.x,q1.y},{q1.z,q1.w},\
                             {q2.x,q2.y},{q2.z,q2.w},{q3.x,q3.y},{q3.z,q3.w}};\
        /* 4 accumulate chains of depth 4 (champion config) */               \
        float cP0[4] = {0,0,0,0}, cQ0[4] = {0,0,0,0};                        \
        float cP1[4] = {0,0,0,0}, cQ1[4] = {0,0,0,0};                        \
        _Pragma("unroll")                                                    \
        for (int kp = 0; kp < 4; kp++) {                                     \
            MMA(cP0, EA[0][2*kp],   rb[2*kp]);                               \
            MMA(cP1, EA[1][2*kp],   rb[2*kp]);                               \
            MMA(cQ0, EA[0][2*kp+1], rb[2*kp+1]);                             \
            MMA(cQ1, EA[1][2*kp+1], rb[2*kp+1]);                             \
        }                                                                    \
        s0 = (cP0[0] + cQ0[0]) * ez0;   /* state m0      */                  \
        s1 = (cP0[2] + cQ0[2]) * ez1;   /* state m0 + 8  */                  \
        s2 = (cP1[0] + cQ1[0]) * ez2;   /* state m0 + 16 */                  \
        s3 = (cP1[2] + cQ1[2]) * ez3;   /* state m0 + 24 */                  \
        SD[0] = __float2bfloat16_rn(s0);                                     \
        SD[2] = __float2bfloat16_rn(s1);                                     \
        SD[4] = __float2bfloat16_rn(s2);                                     \
        SD[6] = __float2bfloat16_rn(s3);                                     \
        unsigned mm = max(max(__float_as_uint(s0), __float_as_uint(s1)),     \
                          max(__float_as_uint(s2), __float_as_uint(s3)));    \
        mm = __reduce_max_sync(0xffffffffu, mm);                             \
        if (lane == 0) wmax[DST][warp] = mm;                                 \
        const float* yq = (yp < ylast) ? yp : ylast;                         \
        _Pragma("unroll")                                                    \
        for (int k = 0; k < 4; k++) {                                        \
            ey[k] = __expf(yA[k]);                                           \
            yA[k] = yB[k];                                                   \
            yB[k] = yq[8 * k];                                               \
        }                                                                    \
        yp += KDIM;                                                          \
        __syncthreads();                                                     \
    }

    const int len2 = len & ~1;
    for (int t = 0; t < len2; t += 2) {
        STEP(0, 1, sd1)
        STEP(1, 0, sd0)
    }
    if (len & 1) {
        STEP(0, 1, sd1)
    }
#undef STEP

    // ---- final: out[b] = log(sum_i s_i) + eacc*ln2 ----
    // each state held by 4 lanes (tig duplicates) -> warp sum = 4x partial
    float e = (s0 + s1) + (s2 + s3);
    e += __shfl_xor_sync(0xffffffffu, e, 16);
    e += __shfl_xor_sync(0xffffffffu, e, 8);
    e += __shfl_xor_sync(0xffffffffu, e, 4);
    e += __shfl_xor_sync(0xffffffffu, e, 2);
    e += __shfl_xor_sync(0xffffffffu, e, 1);
    if (lane == 0) redf[warp] = e;
    __syncthreads();
    if (tid == 0) {
        float tot = ((redf[0] + redf[1]) + (redf[2] + redf[3])) * 0.25f;
        out[b] = logf(tot) + (float)((double)eacc * 0.6931471805599453);
    }
}

extern "C" void kernel_launch(void* const* d_in, const int* in_sizes, int n_in,
                              void* d_out, int out_size) {
    const float* y     = (const float*)d_in[0];   // (B, T, K) f32
    const float* mask  = (const float*)d_in[1];   // (B, T)    f32
    const float* trans = (const float*)d_in[2];   // (K, K)    f32
    float* out = (float*)d_out;                   // (B,)      f32

    const int B = out_size;                       // 64
    const int T = in_sizes[1] / B;                // 256

    crf_fwd_kernel<<<B, 128>>>(y, mask, trans, out, T);
}